// round 10
// baseline (speedup 1.0000x reference)
#include <cuda_runtime.h>
#include <cuda_bf16.h>
#include <cstdint>

// LSTMModel: B=4096, T=512, D=8, H=64, 2 layers + FC(64->1)
//
// R10 = R9 resubmitted (R9 bench hit infra error 802 "system not yet
// initialized" in harness init — kernel never ran).
//
// Design: R5 phase structure + 512 threads/block (4 warps/SMSP):
//  - 128 blocks x 512 threads, 32 batch/block, all weights in smem (~222 KB).
//  - Thread (j = tid>>3, g = tid&7): 4 gate rows of unit j for 4 batch
//    (2 f32x2 batch-pairs). fma.rn.f32x2 inner product.
//  - Warp = 8 j x 8 g? no: warp covers 4 j x 8 g -> weight LDS.128 broadcast
//    (1 wf); h LDS.128 16B x 8 groups = 32 banks exactly (1 wf, conflict-free).
//  - Phases per step (3 barriers):
//      A: z0 = Wih0@x + Whh0@h0_old
//      bar1
//      C: z1 += Whh1@h1_old  INTERLEAVED with cell0 (MUFU hidden), stage x
//      bar2
//      E: z1 += Wih1@h0_new
//      bar3
//      F: cell1 -> h1   (no barrier: overlaps next step's A)

#define ULL unsigned long long

static __device__ __forceinline__ ULL pk2(float v) {
    ULL r; asm("mov.b64 %0, {%1, %1};" : "=l"(r) : "f"(v)); return r;
}
static __device__ __forceinline__ ULL pkf2(float a, float b) {
    ULL r; asm("mov.b64 %0, {%1, %2};" : "=l"(r) : "f"(a), "f"(b)); return r;
}
static __device__ __forceinline__ float2 upk(ULL v) {
    float2 f; asm("mov.b64 {%0, %1}, %2;" : "=f"(f.x), "=f"(f.y) : "l"(v)); return f;
}
static __device__ __forceinline__ ULL ffma2(ULL a, ULL b, ULL c) {
    ULL d; asm("fma.rn.f32x2 %0, %1, %2, %3;" : "=l"(d) : "l"(a), "l"(b), "l"(c)); return d;
}
static __device__ __forceinline__ float ex2f(float x) {
    float r; asm("ex2.approx.f32 %0, %1;" : "=f"(r) : "f"(x)); return r;
}
static __device__ __forceinline__ float rcpf(float x) {
    float r; asm("rcp.approx.f32 %0, %1;" : "=f"(r) : "f"(x)); return r;
}
static __device__ __forceinline__ float sigm(float x) {
    return rcpf(1.0f + ex2f(-1.4426950408889634f * x));
}
static __device__ __forceinline__ float tanh_fast(float x) {
    float ax = fabsf(x);
    float p = ex2f(-2.8853900817779268f * ax);
    float r = (1.0f - p) * rcpf(1.0f + p);
    return copysignf(r, x);
}

static constexpr int B = 4096;
static constexpr int T = 512;
static constexpr int D = 8;
static constexpr int NBATCH_BLK = 32;
static constexpr int NTHREADS = 512;
static constexpr int HSTRIDE = 36;      // padded row stride (floats) for h state

// smem float offsets (identical to R3/R5)
static constexpr int OFF_WIH0 = 0;                    //  8*256
static constexpr int OFF_WHH0 = OFF_WIH0 + 2048;      // 64*256
static constexpr int OFF_WIH1 = OFF_WHH0 + 16384;     // 64*256
static constexpr int OFF_WHH1 = OFF_WIH1 + 16384;     // 64*256
static constexpr int OFF_B0   = OFF_WHH1 + 16384;     // 256
static constexpr int OFF_B1   = OFF_B0 + 256;         // 256
static constexpr int OFF_WFC  = OFF_B1 + 256;         // 64
static constexpr int OFF_H0   = OFF_WFC + 64;         // 64*36
static constexpr int OFF_H1   = OFF_H0 + 64 * HSTRIDE;// 64*36
static constexpr int OFF_XS   = OFF_H1 + 64 * HSTRIDE;// 2*256
static constexpr int SMEM_FLOATS = OFF_XS + 512;
static constexpr int SMEM_BYTES = SMEM_FLOATS * 4;    // 227,584 B

// Accumulate 4 gates x 2 batch-pairs from one k-slice into a[q*2+p].
// wb: &W[k][j*4] (LDS.128, broadcast)   hb: 2 pairs (1x LDS.128)
static __device__ __forceinline__ void acc_step(ULL (&a)[8],
                                                const float* __restrict__ wb,
                                                const float* __restrict__ hb) {
    float4 w = *(const float4*)(wb);
    ulonglong2 hA = *(const ulonglong2*)(hb);
    ULL h0 = hA.x, h1 = hA.y;
    ULL w0 = pk2(w.x), w1 = pk2(w.y), w2 = pk2(w.z), w3 = pk2(w.w);
    a[0] = ffma2(w0, h0, a[0]); a[1] = ffma2(w0, h1, a[1]);
    a[2] = ffma2(w1, h0, a[2]); a[3] = ffma2(w1, h1, a[3]);
    a[4] = ffma2(w2, h0, a[4]); a[5] = ffma2(w2, h1, a[5]);
    a[6] = ffma2(w3, h0, a[6]); a[7] = ffma2(w3, h1, a[7]);
}

static __device__ __forceinline__ void init_acc(ULL (&a)[8], float4 bz) {
    a[0] = a[1] = pk2(bz.x);
    a[2] = a[3] = pk2(bz.y);
    a[4] = a[5] = pk2(bz.z);
    a[6] = a[7] = pk2(bz.w);
}

// LSTM cell for one batch-pair p (0/1). Returns packed h, updates packed c.
static __device__ __forceinline__ ULL cell_pair(const ULL (&a)[8], int p, ULL& c) {
    float2 i2 = upk(a[p]), f2 = upk(a[2 + p]), g2 = upk(a[4 + p]), o2 = upk(a[6 + p]);
    float2 c2 = upk(c);
    float i0 = sigm(i2.x), f0 = sigm(f2.x), g0 = tanh_fast(g2.x), o0 = sigm(o2.x);
    float i1 = sigm(i2.y), f1 = sigm(f2.y), g1 = tanh_fast(g2.y), o1 = sigm(o2.y);
    float cn0 = f0 * c2.x + i0 * g0;
    float cn1 = f1 * c2.y + i1 * g1;
    c = pkf2(cn0, cn1);
    return pkf2(o0 * tanh_fast(cn0), o1 * tanh_fast(cn1));
}

extern __shared__ float sm[];

__global__ void __launch_bounds__(NTHREADS, 1)
lstm_kernel(const float* __restrict__ x,
            const float* __restrict__ Wih0, const float* __restrict__ Whh0,
            const float* __restrict__ bih0, const float* __restrict__ bhh0,
            const float* __restrict__ Wih1, const float* __restrict__ Whh1,
            const float* __restrict__ bih1, const float* __restrict__ bhh1,
            const float* __restrict__ Wfc,  const float* __restrict__ bfc,
            float* __restrict__ out)
{
    const int tid = threadIdx.x;
    const int j = tid >> 3;        // hidden unit 0..63
    const int g = tid & 7;         // batch group 0..7: batch 4g..4g+3
    const int Bb = blockIdx.x * NBATCH_BLK;

    // ---- load + transpose weights into smem ----
    for (int idx = tid; idx < 2048; idx += NTHREADS) {
        int d = idx >> 8, r = idx & 255, jj = r >> 2, q = r & 3;
        sm[OFF_WIH0 + idx] = Wih0[(q * 64 + jj) * 8 + d];
    }
    for (int idx = tid; idx < 16384; idx += NTHREADS) {
        int k = idx >> 8, r = idx & 255, jj = r >> 2, q = r & 3;
        int row = (q * 64 + jj) * 64 + k;
        sm[OFF_WHH0 + idx] = Whh0[row];
        sm[OFF_WIH1 + idx] = Wih1[row];
        sm[OFF_WHH1 + idx] = Whh1[row];
    }
    if (tid < 256) {
        int jj = tid >> 2, q = tid & 3;
        sm[OFF_B0 + tid] = bih0[q * 64 + jj] + bhh0[q * 64 + jj];
        sm[OFF_B1 + tid] = bih1[q * 64 + jj] + bhh1[q * 64 + jj];
    }
    if (tid < 64) sm[OFF_WFC + tid] = Wfc[tid];
    for (int idx = tid; idx < 2 * 64 * HSTRIDE; idx += NTHREADS)
        sm[OFF_H0 + idx] = 0.0f;   // zero h0 and h1 (contiguous)

    // x prefetch mapping (threads 0-255 only): thread loads x[Bb + bl][t][dl]
    const int bl = tid >> 3;       // 0..31 when tid < 256
    const int dl = tid & 7;        // 0..7
    const float* xptr = x + (size_t)(Bb + (bl & 31)) * (T * D) + dl;
    float x0 = 0.0f;
    if (tid < 256) x0 = __ldg(xptr);
    __syncthreads();
    if (tid < 256) sm[OFF_XS + dl * 32 + bl] = x0;

    ULL c0[2] = {0, 0};            // packed cell state, layer 0 (2 pairs)
    ULL c1[2] = {0, 0};            // layer 1

    const int hoff = g * 4;        // float offset of this group's 2 pairs
    float* h0dst = sm + OFF_H0 + j * HSTRIDE + hoff;
    float* h1dst = sm + OFF_H1 + j * HSTRIDE + hoff;
    const float4 b0v = *(const float4*)(sm + OFF_B0 + j * 4);
    const float4 b1v = *(const float4*)(sm + OFF_B1 + j * 4);
    const int jw = j * 4;

    __syncthreads();   // weights + x stage for t=0 visible

    ULL a0[8], a1[8];

    for (int t = 0; t < T; ++t) {
        const int cur = (t & 1) * 256;
        const int nxt = 256 - cur;
        float xn = 0.0f;
        if (tid < 256 && t + 1 < T) xn = __ldg(xptr + (t + 1) * D);

        // ---------- phase A: z0 = x@Wih0^T + h0_old@Whh0^T ----------
        init_acc(a0, b0v);
        #pragma unroll
        for (int d = 0; d < D; ++d)
            acc_step(a0, sm + OFF_WIH0 + d * 256 + jw, sm + OFF_XS + cur + d * 32 + hoff);
        #pragma unroll 8
        for (int k = 0; k < 64; ++k)
            acc_step(a0, sm + OFF_WHH0 + k * 256 + jw, sm + OFF_H0 + k * HSTRIDE + hoff);

        __syncthreads();   // bar1: reads of h0_old + xs(cur) done; F(t-1) h1 writes fenced

        // ---------- phase C: z1 += Whh1@h1_old, interleaved with cell0 ----------
        init_acc(a1, b1v);
        #pragma unroll
        for (int p = 0; p < 2; ++p) {
            #pragma unroll
            for (int k = p * 32; k < p * 32 + 32; ++k)
                acc_step(a1, sm + OFF_WHH1 + k * 256 + jw, sm + OFF_H1 + k * HSTRIDE + hoff);
            ULL hp = cell_pair(a0, p, c0[p]);
            *(ULL*)(h0dst + 2 * p) = hp;
        }
        if (tid < 256) sm[OFF_XS + nxt + dl * 32 + bl] = xn;   // stage next x

        __syncthreads();   // bar2: h0_new + xs(next) visible; h1_old reads done

        // ---------- phase E: z1 += Wih1@h0_new ----------
        #pragma unroll 8
        for (int k = 0; k < 64; ++k)
            acc_step(a1, sm + OFF_WIH1 + k * 256 + jw, sm + OFF_H0 + k * HSTRIDE + hoff);

        __syncthreads();   // bar3: all z1 inputs consumed

        // ---------- phase F: cell1 -> h1 (overlaps next step's phase A) ----------
        #pragma unroll
        for (int p = 0; p < 2; ++p) {
            ULL hp = cell_pair(a1, p, c1[p]);
            *(ULL*)(h1dst + 2 * p) = hp;
        }
        // no trailing barrier: next A reads only h0/xs (disjoint); C(t+1)'s
        // h1 reads are fenced by bar1(t+1).
    }

    __syncthreads();       // final h1 visible

    // ---------- FC head: out[b] = h1[b] . Wfc + bfc ----------
    if (tid < NBATCH_BLK) {
        float acc2 = __ldg(bfc);
        #pragma unroll 8
        for (int k = 0; k < 64; ++k)
            acc2 += sm[OFF_H1 + k * HSTRIDE + tid] * sm[OFF_WFC + k];
        out[Bb + tid] = acc2;
    }
}

extern "C" void kernel_launch(void* const* d_in, const int* in_sizes, int n_in,
                              void* d_out, int out_size) {
    (void)in_sizes; (void)n_in; (void)out_size;
    const float* x    = (const float*)d_in[0];
    const float* Wih0 = (const float*)d_in[1];
    const float* Whh0 = (const float*)d_in[2];
    const float* bih0 = (const float*)d_in[3];
    const float* bhh0 = (const float*)d_in[4];
    const float* Wih1 = (const float*)d_in[5];
    const float* Whh1 = (const float*)d_in[6];
    const float* bih1 = (const float*)d_in[7];
    const float* bhh1 = (const float*)d_in[8];
    const float* Wfc  = (const float*)d_in[9];
    const float* bfc  = (const float*)d_in[10];
    float* out = (float*)d_out;

    cudaFuncSetAttribute(lstm_kernel,
                         cudaFuncAttributeMaxDynamicSharedMemorySize, SMEM_BYTES);
    lstm_kernel<<<B / NBATCH_BLK, NTHREADS, SMEM_BYTES>>>(
        x, Wih0, Whh0, bih0, bhh0, Wih1, Whh1, bih1, bhh1, Wfc, bfc, out);
}